// round 1
// baseline (speedup 1.0000x reference)
#include <cuda_runtime.h>
#include <math.h>

#define BATCH 8
#define SEQ   2048
#define DIM   320
#define NHEAD 5
#define HDIM  64
#define FFD   864
#define NLAYER 6
#define KSEL  1638
#define NTOK  (BATCH*SEQ)      // 16384
#define NSEL  (BATCH*KSEL)     // 13104
#define QKVN  (3*DIM)          // 960

// ---------------- scratch (static device allocations; no cudaMalloc) ----------------
__device__ float g_h[(size_t)NTOK*DIM];
__device__ float g_qkv[(size_t)NTOK*QKVN];
__device__ float g_attn[(size_t)NTOK*DIM];
__device__ float g_hs[(size_t)NSEL*DIM];
__device__ float g_gate[(size_t)NSEL*FFD];
__device__ float g_up[(size_t)NSEL*FFD];
__device__ float g_mlp[(size_t)NSEL*DIM];
__device__ float g_cos[SEQ*32];
__device__ float g_sin[SEQ*32];
__device__ int   g_tk_idx[BATCH*KSEL];
__device__ float g_tk_p[BATCH*KSEL];

// ---------------- RoPE tables ----------------
__global__ void rope_table_k() {
    int i = blockIdx.x*blockDim.x + threadIdx.x;
    if (i >= SEQ*32) return;
    int s = i >> 5, d = i & 31;
    double freq = exp(-((double)(2*d)/(double)HDIM) * log(10000.0));
    double a = (double)s * freq;
    g_cos[i] = (float)cos(a);
    g_sin[i] = (float)sin(a);
}

// ---------------- embedding + iter_emb ----------------
__global__ void embed_k(const int* __restrict__ ids, const int* __restrict__ iter,
                        const float* __restrict__ emb, const float* __restrict__ iter_emb,
                        float* __restrict__ x) {
    int i = blockIdx.x*blockDim.x + threadIdx.x;
    if (i >= NTOK*DIM) return;
    int tok = i / DIM, d = i - tok*DIM;
    int it = iter[0];   // low 32 bits; value is small & non-negative
    float v = emb[(size_t)ids[tok]*DIM + d];
    if (it < 8) v += iter_emb[(size_t)it*DIM + d];
    x[i] = v;
}

// ---------------- rmsnorm (optionally gathered rows) ----------------
__global__ void rmsnorm_k(const float* __restrict__ in, const float* __restrict__ w,
                          float* __restrict__ out, int gather) {
    int r = blockIdx.x, t = threadIdx.x;   // 320 threads
    size_t src;
    if (gather) {
        int b = r / KSEL;
        src = ((size_t)b*SEQ + g_tk_idx[r]) * DIM;
    } else {
        src = (size_t)r * DIM;
    }
    float v = in[src + t];
    float sq = v*v;
    #pragma unroll
    for (int o = 16; o > 0; o >>= 1) sq += __shfl_down_sync(0xffffffffu, sq, o);
    __shared__ float wsum[10];
    __shared__ float s_inv;
    if ((t & 31) == 0) wsum[t >> 5] = sq;
    __syncthreads();
    if (t == 0) {
        float s = 0.f;
        #pragma unroll
        for (int i = 0; i < 10; i++) s += wsum[i];
        s_inv = rsqrtf(s / (float)DIM + 1e-6f);
    }
    __syncthreads();
    out[(size_t)r*DIM + t] = w[t] * v * s_inv;
}

// ---------------- generic NT SGEMM: C[M,N] = A[M,K] @ B[N,K]^T (+C if acc) ----------------
#define BM 64
#define BN 64
#define BK 16
__global__ __launch_bounds__(256)
void gemm_nt_k(const float* __restrict__ A, const float* __restrict__ B,
               float* __restrict__ C, int M, int N, int K, int acc) {
    __shared__ float As[BK][BM+4];
    __shared__ float Bs[BK][BN+4];
    int m0 = blockIdx.y*BM, n0 = blockIdx.x*BN;
    int t = threadIdx.x;
    int ty = t >> 4, tx = t & 15;
    int lr = t >> 2;          // 0..63
    int lk = (t & 3) * 4;     // 0,4,8,12
    float cacc[4][4] = {};
    for (int k0 = 0; k0 < K; k0 += BK) {
        float4 av = make_float4(0.f,0.f,0.f,0.f);
        float4 bv = make_float4(0.f,0.f,0.f,0.f);
        if (m0 + lr < M) av = *(const float4*)(A + (size_t)(m0+lr)*K + k0 + lk);
        if (n0 + lr < N) bv = *(const float4*)(B + (size_t)(n0+lr)*K + k0 + lk);
        __syncthreads();
        As[lk+0][lr]=av.x; As[lk+1][lr]=av.y; As[lk+2][lr]=av.z; As[lk+3][lr]=av.w;
        Bs[lk+0][lr]=bv.x; Bs[lk+1][lr]=bv.y; Bs[lk+2][lr]=bv.z; Bs[lk+3][lr]=bv.w;
        __syncthreads();
        #pragma unroll
        for (int k = 0; k < BK; k++) {
            float4 a = *(const float4*)&As[k][ty*4];
            float4 b = *(const float4*)&Bs[k][tx*4];
            cacc[0][0] += a.x*b.x; cacc[0][1] += a.x*b.y; cacc[0][2] += a.x*b.z; cacc[0][3] += a.x*b.w;
            cacc[1][0] += a.y*b.x; cacc[1][1] += a.y*b.y; cacc[1][2] += a.y*b.z; cacc[1][3] += a.y*b.w;
            cacc[2][0] += a.z*b.x; cacc[2][1] += a.z*b.y; cacc[2][2] += a.z*b.z; cacc[2][3] += a.z*b.w;
            cacc[3][0] += a.w*b.x; cacc[3][1] += a.w*b.y; cacc[3][2] += a.w*b.z; cacc[3][3] += a.w*b.w;
        }
    }
    #pragma unroll
    for (int i = 0; i < 4; i++) {
        int m = m0 + ty*4 + i;
        if (m >= M) continue;
        #pragma unroll
        for (int j = 0; j < 4; j++) {
            int n = n0 + tx*4 + j;
            if (n >= N) continue;
            size_t o = (size_t)m*N + n;
            float v = cacc[i][j];
            if (acc) v += C[o];
            C[o] = v;
        }
    }
}

// ---------------- RoPE on q,k sections of qkv ----------------
__global__ void rope_k(float* __restrict__ qkv) {
    int i = blockIdx.x*blockDim.x + threadIdx.x; // NTOK * 320 pairs
    if (i >= NTOK*320) return;
    int tok = i / 320, rest = i - tok*320;
    int part = rest / 160;              // 0=q, 1=k
    int rr = rest - part*160;
    int h = rr >> 5, d = rr & 31;
    int s = tok & (SEQ-1);
    float c = g_cos[s*32 + d], sn = g_sin[s*32 + d];
    float* p = qkv + (size_t)tok*QKVN + part*DIM + h*HDIM;
    float a = p[d], b = p[d+32];
    p[d]    = a*c - b*sn;
    p[d+32] = b*c + a*sn;
}

// ---------------- causal attention, online softmax, one block per (b,h,q) ----------------
__global__ __launch_bounds__(128)
void attn_k(const float* __restrict__ qkv, float* __restrict__ out) {
    int q = blockIdx.x, h = blockIdx.y, b = blockIdx.z;
    int t = threadIdx.x;                // 128
    __shared__ float qs[HDIM];
    __shared__ float pbuf[128];
    __shared__ float red[128];
    const float* base = qkv + (size_t)b*SEQ*QKVN;
    if (t < HDIM) qs[t] = base[(size_t)q*QKVN + h*HDIM + t] * 0.125f;
    __syncthreads();
    float m_reg = -1e30f, sum_reg = 0.f, accA = 0.f;
    int d = t & 63, half = t >> 6;
    const float* vcol = base + 2*DIM + h*HDIM + d;
    for (int k0 = 0; k0 <= q; k0 += 128) {
        int kk = k0 + t;
        float s = -1e30f;
        if (kk <= q) {
            const float4* kp = (const float4*)(base + (size_t)kk*QKVN + DIM + h*HDIM);
            const float4* qp = (const float4*)qs;
            float acc = 0.f;
            #pragma unroll
            for (int d2 = 0; d2 < 16; d2++) {
                float4 kv = kp[d2], qv = qp[d2];
                acc += qv.x*kv.x + qv.y*kv.y + qv.z*kv.z + qv.w*kv.w;
            }
            s = acc;
        }
        red[t] = s; __syncthreads();
        #pragma unroll
        for (int o = 64; o > 0; o >>= 1) { if (t < o) red[t] = fmaxf(red[t], red[t+o]); __syncthreads(); }
        float cmax = red[0];
        float mnew = fmaxf(m_reg, cmax);
        float corr = expf(m_reg - mnew);
        float p = (kk <= q) ? expf(s - mnew) : 0.f;
        m_reg = mnew;
        __syncthreads();
        red[t] = p; pbuf[t] = p;
        __syncthreads();
        #pragma unroll
        for (int o = 64; o > 0; o >>= 1) { if (t < o) red[t] += red[t+o]; __syncthreads(); }
        sum_reg = sum_reg * corr + red[0];
        accA *= corr;
        #pragma unroll 4
        for (int j = half; j < 128; j += 2)
            accA += pbuf[j] * vcol[(size_t)(k0+j)*QKVN];
        __syncthreads();
    }
    red[t] = accA; __syncthreads();
    if (t < HDIM)
        out[((size_t)b*SEQ + q)*DIM + h*HDIM + t] = (red[t] + red[t+64]) / sum_reg;
}

// ---------------- router + top-k (per-batch bitonic sort) ----------------
__global__ __launch_bounds__(1024)
void router_topk_k(const float* __restrict__ x, const float* __restrict__ rw) {
    int b = blockIdx.x, t = threadIdx.x;
    __shared__ float rws[DIM];
    __shared__ float ps[SEQ];
    __shared__ int   is[SEQ];
    for (int i = t; i < DIM; i += 1024) rws[i] = rw[i];
    __syncthreads();
    for (int s = t; s < SEQ; s += 1024) {
        const float* row = x + ((size_t)b*SEQ + s)*DIM;
        float acc = 0.f;
        for (int dd = 0; dd < DIM; dd++) acc += row[dd]*rws[dd];
        ps[s] = 1.f/(1.f + expf(-acc));
        is[s] = s;
    }
    __syncthreads();
    // bitonic sort, best-first (desc prob, ties -> smaller idx first like jax.lax.top_k)
    for (int size = 2; size <= SEQ; size <<= 1) {
        for (int stride = size >> 1; stride > 0; stride >>= 1) {
            for (int i = t; i < SEQ; i += 1024) {
                int j = i ^ stride;
                if (j > i) {
                    bool up = ((i & size) == 0);
                    float pi = ps[i], pj = ps[j];
                    int ii = is[i], ij = is[j];
                    bool iBetter = (pi > pj) || (pi == pj && ii < ij);
                    if (iBetter != up) { ps[i] = pj; ps[j] = pi; is[i] = ij; is[j] = ii; }
                }
            }
            __syncthreads();
        }
    }
    for (int jj = t; jj < KSEL; jj += 1024) {
        g_tk_idx[b*KSEL + jj] = is[jj];
        g_tk_p[b*KSEL + jj]   = ps[jj];
    }
}

// ---------------- silu(gate)*up, in place into gate buffer ----------------
__global__ void act_k(float* __restrict__ g, const float* __restrict__ u, int n) {
    int i = blockIdx.x*blockDim.x + threadIdx.x;
    if (i >= n) return;
    float v = g[i];
    g[i] = (v / (1.f + expf(-v))) * u[i];
}

// ---------------- scatter-add mlp * prob back into x ----------------
__global__ void scatter_k(float* __restrict__ x, const float* __restrict__ mlp) {
    int i = blockIdx.x*blockDim.x + threadIdx.x;
    if (i >= NSEL*DIM) return;
    int g = i / DIM, d = i - g*DIM;
    int b = g / KSEL;
    int srow = g_tk_idx[g];
    x[((size_t)b*SEQ + srow)*DIM + d] += mlp[i] * g_tk_p[g];
}

// ---------------- host orchestration ----------------
extern "C" void kernel_launch(void* const* d_in, const int* in_sizes, int n_in,
                              void* d_out, int out_size) {
    const int*   ids       = (const int*)d_in[0];
    const int*   iter      = (const int*)d_in[1];
    const float* emb       = (const float*)d_in[2];
    const float* iter_emb  = (const float*)d_in[3];
    const float* attn_norm = (const float*)d_in[4];
    const float* wqkv      = (const float*)d_in[5];
    const float* wo        = (const float*)d_in[6];
    const float* router    = (const float*)d_in[7];
    const float* mlp_norm  = (const float*)d_in[8];
    const float* gw        = (const float*)d_in[9];
    const float* uw        = (const float*)d_in[10];
    const float* dw        = (const float*)d_in[11];
    const float* fnorm     = (const float*)d_in[12];
    float* x = (float*)d_out;

    float *ph, *pqkv, *pattn, *phs, *pgate, *pup, *pmlp;
    cudaGetSymbolAddress((void**)&ph,    g_h);
    cudaGetSymbolAddress((void**)&pqkv,  g_qkv);
    cudaGetSymbolAddress((void**)&pattn, g_attn);
    cudaGetSymbolAddress((void**)&phs,   g_hs);
    cudaGetSymbolAddress((void**)&pgate, g_gate);
    cudaGetSymbolAddress((void**)&pup,   g_up);
    cudaGetSymbolAddress((void**)&pmlp,  g_mlp);

    rope_table_k<<<(SEQ*32 + 255)/256, 256>>>();
    embed_k<<<(NTOK*DIM + 255)/256, 256>>>(ids, iter, emb, iter_emb, x);

    for (int l = 0; l < NLAYER; l++) {
        rmsnorm_k<<<NTOK, DIM>>>(x, attn_norm + (size_t)l*DIM, ph, 0);

        gemm_nt_k<<<dim3((QKVN+BN-1)/BN, (NTOK+BM-1)/BM), 256>>>(
            ph, wqkv + (size_t)l*QKVN*DIM, pqkv, NTOK, QKVN, DIM, 0);

        rope_k<<<(NTOK*320 + 255)/256, 256>>>(pqkv);

        attn_k<<<dim3(SEQ, NHEAD, BATCH), 128>>>(pqkv, pattn);

        gemm_nt_k<<<dim3((DIM+BN-1)/BN, (NTOK+BM-1)/BM), 256>>>(
            pattn, wo + (size_t)l*DIM*DIM, x, NTOK, DIM, DIM, 1);

        router_topk_k<<<BATCH, 1024>>>(x, router + (size_t)l*DIM);

        rmsnorm_k<<<NSEL, DIM>>>(x, mlp_norm + (size_t)l*DIM, phs, 1);

        gemm_nt_k<<<dim3((FFD+BN-1)/BN, (NSEL+BM-1)/BM), 256>>>(
            phs, gw + (size_t)l*FFD*DIM, pgate, NSEL, FFD, DIM, 0);
        gemm_nt_k<<<dim3((FFD+BN-1)/BN, (NSEL+BM-1)/BM), 256>>>(
            phs, uw + (size_t)l*FFD*DIM, pup, NSEL, FFD, DIM, 0);

        act_k<<<(NSEL*FFD + 255)/256, 256>>>(pgate, pup, NSEL*FFD);

        gemm_nt_k<<<dim3((DIM+BN-1)/BN, (NSEL+BM-1)/BM), 256>>>(
            pgate, dw + (size_t)l*DIM*FFD, pmlp, NSEL, DIM, FFD, 0);

        scatter_k<<<(NSEL*DIM + 255)/256, 256>>>(x, pmlp);
    }

    rmsnorm_k<<<NTOK, DIM>>>(x, fnorm, x, 0);
}

// round 3
// speedup vs baseline: 3.9034x; 3.9034x over previous
#include <cuda_runtime.h>
#include <math.h>

#define BATCH 8
#define SEQ   2048
#define DIM   320
#define NHEAD 5
#define HDIM  64
#define FFD   864
#define NLAYER 6
#define KSEL  1638
#define NTOK  (BATCH*SEQ)      // 16384
#define NSEL  (BATCH*KSEL)     // 13104
#define QKVN  (3*DIM)          // 960

// ---------------- scratch (static device allocations; no cudaMalloc) ----------------
__device__ float g_h[(size_t)NTOK*DIM];
__device__ float g_qkv[(size_t)NTOK*QKVN];
__device__ float g_attn[(size_t)NTOK*DIM];
__device__ float g_hs[(size_t)NSEL*DIM];
__device__ float g_gate[(size_t)NSEL*FFD];
__device__ float g_up[(size_t)NSEL*FFD];
__device__ float g_mlp[(size_t)NSEL*DIM];
__device__ float g_cos[SEQ*32];
__device__ float g_sin[SEQ*32];
__device__ int   g_tk_idx[BATCH*KSEL];
__device__ float g_tk_p[BATCH*KSEL];
__device__ float g_probs[NTOK];

// ---------------- RoPE tables ----------------
__global__ void rope_table_k() {
    int i = blockIdx.x*blockDim.x + threadIdx.x;
    if (i >= SEQ*32) return;
    int s = i >> 5, d = i & 31;
    double freq = exp(-((double)(2*d)/(double)HDIM) * log(10000.0));
    double a = (double)s * freq;
    g_cos[i] = (float)cos(a);
    g_sin[i] = (float)sin(a);
}

// ---------------- embedding + iter_emb ----------------
__global__ void embed_k(const int* __restrict__ ids, const int* __restrict__ iter,
                        const float* __restrict__ emb, const float* __restrict__ iter_emb,
                        float* __restrict__ x) {
    int i = blockIdx.x*blockDim.x + threadIdx.x;
    if (i >= NTOK*DIM) return;
    int tok = i / DIM, d = i - tok*DIM;
    int it = iter[0];
    float v = emb[(size_t)ids[tok]*DIM + d];
    if (it < 8) v += iter_emb[(size_t)it*DIM + d];
    x[i] = v;
}

// ---------------- rmsnorm (optionally gathered rows) ----------------
__global__ void rmsnorm_k(const float* __restrict__ in, const float* __restrict__ w,
                          float* __restrict__ out, int gather) {
    int r = blockIdx.x, t = threadIdx.x;   // 320 threads
    size_t src;
    if (gather) {
        int b = r / KSEL;
        src = ((size_t)b*SEQ + g_tk_idx[r]) * DIM;
    } else {
        src = (size_t)r * DIM;
    }
    float v = in[src + t];
    float sq = v*v;
    #pragma unroll
    for (int o = 16; o > 0; o >>= 1) sq += __shfl_down_sync(0xffffffffu, sq, o);
    __shared__ float wsum[10];
    __shared__ float s_inv;
    if ((t & 31) == 0) wsum[t >> 5] = sq;
    __syncthreads();
    if (t == 0) {
        float s = 0.f;
        #pragma unroll
        for (int i = 0; i < 10; i++) s += wsum[i];
        s_inv = rsqrtf(s / (float)DIM + 1e-6f);
    }
    __syncthreads();
    out[(size_t)r*DIM + t] = w[t] * v * s_inv;
}

// ---------------- NT SGEMM 128x128x8, 8x8 micro (split 64+64): C = A@B^T (+C) ----------------
__global__ __launch_bounds__(256)
void gemm_nt128_k(const float* __restrict__ A, const float* __restrict__ B,
                  float* __restrict__ C, int M, int N, int K, int acc) {
    __shared__ float As[8][128];
    __shared__ float Bs[8][128];
    int m0 = blockIdx.y*128, n0 = blockIdx.x*128;
    int t = threadIdx.x;
    int ty = t >> 4, tx = t & 15;
    int lr = t >> 1;          // 0..127
    int lc = (t & 1) * 4;     // 0 or 4
    float acc8[8][8];
    #pragma unroll
    for (int i = 0; i < 8; i++)
        #pragma unroll
        for (int j = 0; j < 8; j++) acc8[i][j] = 0.f;

    const float* Ap = A + (size_t)(m0+lr)*K + lc;
    const float* Bp = B + (size_t)(n0+lr)*K + lc;
    bool aok = (m0 + lr) < M;
    bool bok = (n0 + lr) < N;

    for (int k0 = 0; k0 < K; k0 += 8) {
        float4 av = aok ? *(const float4*)(Ap + k0) : make_float4(0.f,0.f,0.f,0.f);
        float4 bv = bok ? *(const float4*)(Bp + k0) : make_float4(0.f,0.f,0.f,0.f);
        __syncthreads();
        As[lc+0][lr]=av.x; As[lc+1][lr]=av.y; As[lc+2][lr]=av.z; As[lc+3][lr]=av.w;
        Bs[lc+0][lr]=bv.x; Bs[lc+1][lr]=bv.y; Bs[lc+2][lr]=bv.z; Bs[lc+3][lr]=bv.w;
        __syncthreads();
        #pragma unroll
        for (int k = 0; k < 8; k++) {
            float a[8], b[8];
            *(float4*)&a[0] = *(const float4*)&As[k][ty*4];
            *(float4*)&a[4] = *(const float4*)&As[k][64 + ty*4];
            *(float4*)&b[0] = *(const float4*)&Bs[k][tx*4];
            *(float4*)&b[4] = *(const float4*)&Bs[k][64 + tx*4];
            #pragma unroll
            for (int i = 0; i < 8; i++)
                #pragma unroll
                for (int j = 0; j < 8; j++)
                    acc8[i][j] += a[i]*b[j];
        }
    }
    #pragma unroll
    for (int ih = 0; ih < 2; ih++)
    #pragma unroll
    for (int i2 = 0; i2 < 4; i2++) {
        int m = m0 + ih*64 + ty*4 + i2;
        if (m >= M) continue;
        #pragma unroll
        for (int jh = 0; jh < 2; jh++) {
            int n = n0 + jh*64 + tx*4;
            if (n >= N) continue;
            float* cp = C + (size_t)m*N + n;
            float4 v;
            v.x = acc8[ih*4+i2][jh*4+0];
            v.y = acc8[ih*4+i2][jh*4+1];
            v.z = acc8[ih*4+i2][jh*4+2];
            v.w = acc8[ih*4+i2][jh*4+3];
            if (acc) {
                float4 o = *(const float4*)cp;
                v.x += o.x; v.y += o.y; v.z += o.z; v.w += o.w;
            }
            *(float4*)cp = v;
        }
    }
}

// ---------------- RoPE on q,k sections of qkv ----------------
__global__ void rope_k(float* __restrict__ qkv) {
    int i = blockIdx.x*blockDim.x + threadIdx.x;
    if (i >= NTOK*320) return;
    int tok = i / 320, rest = i - tok*320;
    int part = rest / 160;
    int rr = rest - part*160;
    int h = rr >> 5, d = rr & 31;
    int s = tok & (SEQ-1);
    float c = g_cos[s*32 + d], sn = g_sin[s*32 + d];
    float* p = qkv + (size_t)tok*QKVN + part*DIM + h*HDIM;
    float a = p[d], b = p[d+32];
    p[d]    = a*c - b*sn;
    p[d+32] = b*c + a*sn;
}

// ---------------- flash attention: block per (b,h,q-tile of 64), 256 threads ----------------
// dyn smem: Qt[64][68] (transposed, scaled), Vs[64][64], KP[64][68] (K transposed; later P[j][i])
#define QT_OFF 0
#define VS_OFF (64*68)
#define KP_OFF (64*68 + 64*64)
#define ATTN_SMEM ((64*68 + 64*64 + 64*68)*4)
__global__ __launch_bounds__(256)
void fattn_k(const float* __restrict__ qkv, float* __restrict__ out) {
    extern __shared__ float sm[];
    float* Qt = sm + QT_OFF;
    float* Vs = sm + VS_OFF;
    float* KP = sm + KP_OFF;
    int qt = gridDim.x - 1 - blockIdx.x;   // heavy tiles first
    int h = blockIdx.y, b = blockIdx.z;
    int q0 = qt*64;
    int t = threadIdx.x;
    int ty = t >> 4, tx = t & 15;
    const float* base = qkv + (size_t)b*SEQ*QKVN;

    int lrow = t >> 2;       // 0..63
    int lf   = t & 3;        // float4 group base

    // load Q transposed + scaled
    {
        const float* src = base + (size_t)(q0 + lrow)*QKVN + h*HDIM;
        #pragma unroll
        for (int p = 0; p < 4; p++) {
            int c4 = lf + p*4;
            float4 v = *(const float4*)(src + c4*4);
            Qt[(c4*4+0)*68 + lrow] = v.x*0.125f;
            Qt[(c4*4+1)*68 + lrow] = v.y*0.125f;
            Qt[(c4*4+2)*68 + lrow] = v.z*0.125f;
            Qt[(c4*4+3)*68 + lrow] = v.w*0.125f;
        }
    }

    float o4[4][4], m[4], l[4];
    #pragma unroll
    for (int i = 0; i < 4; i++) {
        m[i] = -1e30f; l[i] = 0.f;
        #pragma unroll
        for (int j = 0; j < 4; j++) o4[i][j] = 0.f;
    }

    for (int kt = 0; kt <= qt; kt++) {
        int k0 = kt*64;
        __syncthreads();   // prev PV done; Q store visible on first iter
        // load K transposed, V natural
        {
            const float* ksrc = base + (size_t)(k0 + lrow)*QKVN + DIM + h*HDIM;
            const float* vsrc = base + (size_t)(k0 + lrow)*QKVN + 2*DIM + h*HDIM;
            #pragma unroll
            for (int p = 0; p < 4; p++) {
                int c4 = lf + p*4;
                float4 kv = *(const float4*)(ksrc + c4*4);
                KP[(c4*4+0)*68 + lrow] = kv.x;
                KP[(c4*4+1)*68 + lrow] = kv.y;
                KP[(c4*4+2)*68 + lrow] = kv.z;
                KP[(c4*4+3)*68 + lrow] = kv.w;
                *(float4*)&Vs[lrow*64 + c4*4] = *(const float4*)(vsrc + c4*4);
            }
        }
        __syncthreads();
        // S = Q K^T  (rows ty*4+ii, cols tx*4+jj)
        float cacc[4][4];
        #pragma unroll
        for (int i = 0; i < 4; i++)
            #pragma unroll
            for (int j = 0; j < 4; j++) cacc[i][j] = 0.f;
        #pragma unroll 8
        for (int d = 0; d < 64; d++) {
            float4 a4 = *(const float4*)&Qt[d*68 + ty*4];
            float4 b4 = *(const float4*)&KP[d*68 + tx*4];
            float a[4] = {a4.x,a4.y,a4.z,a4.w};
            float bb[4] = {b4.x,b4.y,b4.z,b4.w};
            #pragma unroll
            for (int i = 0; i < 4; i++)
                #pragma unroll
                for (int j = 0; j < 4; j++)
                    cacc[i][j] += a[i]*bb[j];
        }
        // causal mask on diagonal tile
        if (kt == qt) {
            #pragma unroll
            for (int i = 0; i < 4; i++)
                #pragma unroll
                for (int j = 0; j < 4; j++)
                    if (tx*4+j > ty*4+i) cacc[i][j] = -1e30f;
        }
        // online softmax (register-side)
        float corr[4];
        #pragma unroll
        for (int i = 0; i < 4; i++) {
            float mx = fmaxf(fmaxf(cacc[i][0],cacc[i][1]), fmaxf(cacc[i][2],cacc[i][3]));
            #pragma unroll
            for (int o = 1; o < 16; o <<= 1) mx = fmaxf(mx, __shfl_xor_sync(0xffffffffu, mx, o));
            float mnew = fmaxf(m[i], mx);
            corr[i] = expf(m[i] - mnew);
            m[i] = mnew;
            float rs = 0.f;
            #pragma unroll
            for (int j = 0; j < 4; j++) {
                float pv = expf(cacc[i][j] - mnew);
                cacc[i][j] = pv;
                rs += pv;
            }
            #pragma unroll
            for (int o = 1; o < 16; o <<= 1) rs += __shfl_xor_sync(0xffffffffu, rs, o);
            l[i] = l[i]*corr[i] + rs;
            #pragma unroll
            for (int j = 0; j < 4; j++) o4[i][j] *= corr[i];
        }
        __syncthreads();   // all K reads done -> safe to overwrite as P
        // write P transposed: P[j][i]
        #pragma unroll
        for (int i = 0; i < 4; i++)
            #pragma unroll
            for (int j = 0; j < 4; j++)
                KP[(tx*4+j)*68 + ty*4+i] = cacc[i][j];
        __syncthreads();
        // O += P V  (rows ty*4+ii, dims tx*4+dd)
        #pragma unroll 8
        for (int j = 0; j < 64; j++) {
            float p0 = KP[j*68 + ty*4+0];
            float p1 = KP[j*68 + ty*4+1];
            float p2 = KP[j*68 + ty*4+2];
            float p3 = KP[j*68 + ty*4+3];
            float4 v4 = *(const float4*)&Vs[j*64 + tx*4];
            float vv[4] = {v4.x,v4.y,v4.z,v4.w};
            #pragma unroll
            for (int d2 = 0; d2 < 4; d2++) {
                o4[0][d2] += p0*vv[d2];
                o4[1][d2] += p1*vv[d2];
                o4[2][d2] += p2*vv[d2];
                o4[3][d2] += p3*vv[d2];
            }
        }
    }
    // write out
    #pragma unroll
    for (int i = 0; i < 4; i++) {
        float inv = 1.f / l[i];
        float4 v;
        v.x = o4[i][0]*inv; v.y = o4[i][1]*inv; v.z = o4[i][2]*inv; v.w = o4[i][3]*inv;
        *(float4*)(out + ((size_t)b*SEQ + q0 + ty*4+i)*DIM + h*HDIM + tx*4) = v;
    }
}

// ---------------- router probs: warp per token ----------------
__global__ __launch_bounds__(256)
void router_prob_k(const float* __restrict__ x, const float* __restrict__ rw,
                   float* __restrict__ probs) {
    int tok = blockIdx.x*8 + (threadIdx.x >> 5);
    int lane = threadIdx.x & 31;
    if (tok >= NTOK) return;
    const float* row = x + (size_t)tok*DIM;
    float acc = 0.f;
    #pragma unroll
    for (int i = 0; i < 10; i++) acc += row[lane + 32*i]*rw[lane + 32*i];
    #pragma unroll
    for (int o = 16; o > 0; o >>= 1) acc += __shfl_xor_sync(0xffffffffu, acc, o);
    if (lane == 0) probs[tok] = 1.f/(1.f + expf(-acc));
}

// ---------------- top-k (per-batch bitonic sort) ----------------
__global__ __launch_bounds__(1024)
void topk_k(const float* __restrict__ probs) {
    int b = blockIdx.x, t = threadIdx.x;
    __shared__ float ps[SEQ];
    __shared__ int   is[SEQ];
    for (int s = t; s < SEQ; s += 1024) { ps[s] = probs[b*SEQ + s]; is[s] = s; }
    __syncthreads();
    for (int size = 2; size <= SEQ; size <<= 1) {
        for (int stride = size >> 1; stride > 0; stride >>= 1) {
            for (int i = t; i < SEQ; i += 1024) {
                int j = i ^ stride;
                if (j > i) {
                    bool up = ((i & size) == 0);
                    float pi = ps[i], pj = ps[j];
                    int ii = is[i], ij = is[j];
                    bool iBetter = (pi > pj) || (pi == pj && ii < ij);
                    if (iBetter != up) { ps[i] = pj; ps[j] = pi; is[i] = ij; is[j] = ii; }
                }
            }
            __syncthreads();
        }
    }
    for (int jj = t; jj < KSEL; jj += 1024) {
        g_tk_idx[b*KSEL + jj] = is[jj];
        g_tk_p[b*KSEL + jj]   = ps[jj];
    }
}

// ---------------- silu(gate)*up ----------------
__global__ void act_k(float* __restrict__ g, const float* __restrict__ u, int n) {
    int i = blockIdx.x*blockDim.x + threadIdx.x;
    if (i >= n) return;
    float v = g[i];
    g[i] = (v / (1.f + expf(-v))) * u[i];
}

// ---------------- scatter-add mlp * prob back into x ----------------
__global__ void scatter_k(float* __restrict__ x, const float* __restrict__ mlp) {
    int i = blockIdx.x*blockDim.x + threadIdx.x;
    if (i >= NSEL*DIM) return;
    int g = i / DIM, d = i - g*DIM;
    int b = g / KSEL;
    int srow = g_tk_idx[g];
    x[((size_t)b*SEQ + srow)*DIM + d] += mlp[i] * g_tk_p[g];
}

// ---------------- host orchestration ----------------
extern "C" void kernel_launch(void* const* d_in, const int* in_sizes, int n_in,
                              void* d_out, int out_size) {
    const int*   ids       = (const int*)d_in[0];
    const int*   iter      = (const int*)d_in[1];
    const float* emb       = (const float*)d_in[2];
    const float* iter_emb  = (const float*)d_in[3];
    const float* attn_norm = (const float*)d_in[4];
    const float* wqkv      = (const float*)d_in[5];
    const float* wo        = (const float*)d_in[6];
    const float* router    = (const float*)d_in[7];
    const float* mlp_norm  = (const float*)d_in[8];
    const float* gw        = (const float*)d_in[9];
    const float* uw        = (const float*)d_in[10];
    const float* dw        = (const float*)d_in[11];
    const float* fnorm     = (const float*)d_in[12];
    float* x = (float*)d_out;

    float *ph, *pqkv, *pattn, *phs, *pgate, *pup, *pmlp, *pprobs;
    cudaGetSymbolAddress((void**)&ph,    g_h);
    cudaGetSymbolAddress((void**)&pqkv,  g_qkv);
    cudaGetSymbolAddress((void**)&pattn, g_attn);
    cudaGetSymbolAddress((void**)&phs,   g_hs);
    cudaGetSymbolAddress((void**)&pgate, g_gate);
    cudaGetSymbolAddress((void**)&pup,   g_up);
    cudaGetSymbolAddress((void**)&pmlp,  g_mlp);
    cudaGetSymbolAddress((void**)&pprobs,g_probs);

    cudaFuncSetAttribute(fattn_k, cudaFuncAttributeMaxDynamicSharedMemorySize, ATTN_SMEM);

    rope_table_k<<<(SEQ*32 + 255)/256, 256>>>();
    embed_k<<<(NTOK*DIM + 255)/256, 256>>>(ids, iter, emb, iter_emb, x);

    for (int l = 0; l < NLAYER; l++) {
        rmsnorm_k<<<NTOK, DIM>>>(x, attn_norm + (size_t)l*DIM, ph, 0);

        gemm_nt128_k<<<dim3((QKVN+127)/128, (NTOK+127)/128), 256>>>(
            ph, wqkv + (size_t)l*QKVN*DIM, pqkv, NTOK, QKVN, DIM, 0);

        rope_k<<<(NTOK*320 + 255)/256, 256>>>(pqkv);

        fattn_k<<<dim3(SEQ/64, NHEAD, BATCH), 256, ATTN_SMEM>>>(pqkv, pattn);

        gemm_nt128_k<<<dim3((DIM+127)/128, (NTOK+127)/128), 256>>>(
            pattn, wo + (size_t)l*DIM*DIM, x, NTOK, DIM, DIM, 1);

        router_prob_k<<<(NTOK+7)/8, 256>>>(x, router + (size_t)l*DIM, pprobs);
        topk_k<<<BATCH, 1024>>>(pprobs);

        rmsnorm_k<<<NSEL, DIM>>>(x, mlp_norm + (size_t)l*DIM, phs, 1);

        gemm_nt128_k<<<dim3((FFD+127)/128, (NSEL+127)/128), 256>>>(
            phs, gw + (size_t)l*FFD*DIM, pgate, NSEL, FFD, DIM, 0);
        gemm_nt128_k<<<dim3((FFD+127)/128, (NSEL+127)/128), 256>>>(
            phs, uw + (size_t)l*FFD*DIM, pup, NSEL, FFD, DIM, 0);

        act_k<<<(NSEL*FFD + 255)/256, 256>>>(pgate, pup, NSEL*FFD);

        gemm_nt128_k<<<dim3((DIM+127)/128, (NSEL+127)/128), 256>>>(
            pgate, dw + (size_t)l*DIM*FFD, pmlp, NSEL, DIM, FFD, 0);

        scatter_k<<<(NSEL*DIM + 255)/256, 256>>>(x, pmlp);
    }

    rmsnorm_k<<<NTOK, DIM>>>(x, fnorm, x, 0);
}

// round 5
// speedup vs baseline: 5.1080x; 1.3086x over previous
#include <cuda_runtime.h>
#include <cuda_fp16.h>
#include <math.h>
#include <stdint.h>

#define BATCH 8
#define SEQ   2048
#define DIM   320
#define NHEAD 5
#define HDIM  64
#define FFD   864
#define NLAYER 6
#define KSEL  1638
#define NTOK  (BATCH*SEQ)      // 16384
#define NSEL  (BATCH*KSEL)     // 13104
#define QKVN  (3*DIM)          // 960

// weight split buffer offsets (elements)
#define OFF_QKV  0
#define LEN_QKV  (NLAYER*QKVN*DIM)
#define OFF_WO   (OFF_QKV + LEN_QKV)
#define LEN_WO   (NLAYER*DIM*DIM)
#define OFF_GU   (OFF_WO + LEN_WO)
#define LEN_GU   (NLAYER*2*FFD*DIM)
#define OFF_DOWN (OFF_GU + LEN_GU)
#define LEN_DOWN (NLAYER*DIM*FFD)
#define W_TOTAL  (OFF_DOWN + LEN_DOWN)

// ---------------- scratch ----------------
__device__ __half g_shi[(size_t)NSEL*FFD];
__device__ __half g_slo[(size_t)NSEL*FFD];
__device__ __half g_whi[W_TOTAL];
__device__ __half g_wlo[W_TOTAL];
__device__ float g_qkv[(size_t)NTOK*QKVN];
__device__ float g_gu[(size_t)NSEL*2*FFD];
__device__ float g_mlp[(size_t)NSEL*DIM];
__device__ float g_cos[SEQ*32];
__device__ float g_sin[SEQ*32];
__device__ int   g_tk_idx[BATCH*KSEL];
__device__ float g_tk_p[BATCH*KSEL];
__device__ float g_probs[NTOK];

__device__ __forceinline__ void split_h(float v, __half& h, __half& l) {
    h = __float2half_rn(v);
    l = __float2half_rn(v - __half2float(h));
}

// ================= PTX helpers (non-'a' features only) =================
__device__ __forceinline__ uint32_t smem_u32(const void* p) {
    uint32_t a;
    asm("{ .reg .u64 t; cvta.to.shared.u64 t, %1; cvt.u32.u64 %0, t; }" : "=r"(a) : "l"(p));
    return a;
}
__device__ __forceinline__ void cp16(uint32_t dst, const void* src) {
    asm volatile("cp.async.cg.shared.global [%0], [%1], 16;" :: "r"(dst), "l"(src) : "memory");
}
__device__ __forceinline__ uint32_t lds32(uint32_t addr) {
    uint32_t v;
    asm volatile("ld.shared.b32 %0, [%1];" : "=r"(v) : "r"(addr));
    return v;
}
__device__ __forceinline__ void mma16816(float* c, const uint32_t* a, const uint32_t* b) {
    asm volatile("mma.sync.aligned.m16n8k16.row.col.f32.f16.f16.f32 "
        "{%0,%1,%2,%3}, {%4,%5,%6,%7}, {%8,%9}, {%0,%1,%2,%3};"
        : "+f"(c[0]), "+f"(c[1]), "+f"(c[2]), "+f"(c[3])
        : "r"(a[0]), "r"(a[1]), "r"(a[2]), "r"(a[3]), "r"(b[0]), "r"(b[1]));
}

// ================= fp16x3 tensor-core GEMM =================
// C[M,N] (+)= A[M,K] @ B[N,K]^T. A,B given as (hi,lo) fp16 pairs.
// block tile 128x128, K-tile 32, 8 warps (2 m x 4 n), warp tile 64x32.
// smem per stage: A 16KB + B 16KB; rows of 128B = [hi 4 chunks | lo 4 chunks],
// chunk swizzle: phys = chunk ^ (row&7)  -> conflict-free 32-bit frag loads.
__global__ __launch_bounds__(256)
void gemm_h3_k(const __half* __restrict__ Ahi, const __half* __restrict__ Alo,
               const __half* __restrict__ Bhi, const __half* __restrict__ Blo,
               float* __restrict__ C, int M, int N, int K, int acc)
{
    extern __shared__ char smem_raw[];
    uint32_t sb = (smem_u32(smem_raw) + 127u) & ~127u;

    const int t = threadIdx.x, lane = t & 31, wid = t >> 5;
    const int warp_m = wid & 1, warp_n = wid >> 1;
    const int m0 = blockIdx.y*128, n0 = blockIdx.x*128;
    const int T = K >> 5;
    const int l4 = lane >> 2, lm = lane & 3;

    // loader: thread t -> row t>>1, (t&1) selects hi(0)/lo(1) chunk group
    const int lrow = t >> 1;
    const int lhalf = t & 1;
    const int aRow = min(m0 + lrow, M-1);
    const int bRow = min(n0 + lrow, N-1);
    const __half* aSrc = (lhalf ? Alo : Ahi) + (size_t)aRow*K;
    const __half* bSrc = (lhalf ? Blo : Bhi) + (size_t)bRow*K;
    uint32_t aDstBase = sb + (uint32_t)lrow*128u;
    uint32_t bDstBase = sb + 16384u + (uint32_t)lrow*128u;

    auto load_stage = [&](int kt, int s) {
        uint32_t so = (uint32_t)s*32768u;
        int k0 = kt*32;
        #pragma unroll
        for (int c4 = 0; c4 < 4; c4++) {
            int chunk = lhalf*4 + c4;
            uint32_t phys = (uint32_t)((chunk ^ (lrow & 7)) * 16);
            cp16(aDstBase + so + phys, aSrc + k0 + c4*8);
            cp16(bDstBase + so + phys, bSrc + k0 + c4*8);
        }
        asm volatile("cp.async.commit_group;" ::: "memory");
    };

    float accf[4][4][4];
    #pragma unroll
    for (int i = 0; i < 4; i++)
        #pragma unroll
        for (int j = 0; j < 4; j++)
            #pragma unroll
            for (int r = 0; r < 4; r++) accf[i][j][r] = 0.f;

    load_stage(0, 0);

    for (int kt = 0; kt < T; kt++) {
        int s = kt & 1;
        if (kt + 1 < T) {
            load_stage(kt + 1, s ^ 1);
            asm volatile("cp.async.wait_group 1;" ::: "memory");
        } else {
            asm volatile("cp.async.wait_group 0;" ::: "memory");
        }
        __syncthreads();
        uint32_t Ab = sb + (uint32_t)s*32768u;
        uint32_t Bb = Ab + 16384u;
        #pragma unroll
        for (int ks = 0; ks < 2; ks++) {
            uint32_t ah[4][4], al[4][4];
            #pragma unroll
            for (int mf = 0; mf < 4; mf++) {
                int r0 = warp_m*64 + mf*16 + l4;
                int r1 = r0 + 8;
                int ch = ks*2, cl = ks*2 + 1;
                uint32_t a0 = Ab + (uint32_t)(r0*128) + (uint32_t)(lm*4);
                uint32_t a1 = Ab + (uint32_t)(r1*128) + (uint32_t)(lm*4);
                ah[mf][0] = lds32(a0 + (uint32_t)(((ch  ) ^ (r0&7))*16));
                ah[mf][1] = lds32(a1 + (uint32_t)(((ch  ) ^ (r1&7))*16));
                ah[mf][2] = lds32(a0 + (uint32_t)(((cl  ) ^ (r0&7))*16));
                ah[mf][3] = lds32(a1 + (uint32_t)(((cl  ) ^ (r1&7))*16));
                al[mf][0] = lds32(a0 + (uint32_t)(((ch+4) ^ (r0&7))*16));
                al[mf][1] = lds32(a1 + (uint32_t)(((ch+4) ^ (r1&7))*16));
                al[mf][2] = lds32(a0 + (uint32_t)(((cl+4) ^ (r0&7))*16));
                al[mf][3] = lds32(a1 + (uint32_t)(((cl+4) ^ (r1&7))*16));
            }
            #pragma unroll
            for (int nf = 0; nf < 4; nf++) {
                int cB = warp_n*32 + nf*8 + l4;
                int ch = ks*2, cl = ks*2 + 1;
                uint32_t bbase = Bb + (uint32_t)(cB*128) + (uint32_t)(lm*4);
                uint32_t bh[2], bl[2];
                bh[0] = lds32(bbase + (uint32_t)(((ch  ) ^ (cB&7))*16));
                bh[1] = lds32(bbase + (uint32_t)(((cl  ) ^ (cB&7))*16));
                bl[0] = lds32(bbase + (uint32_t)(((ch+4) ^ (cB&7))*16));
                bl[1] = lds32(bbase + (uint32_t)(((cl+4) ^ (cB&7))*16));
                #pragma unroll
                for (int mf = 0; mf < 4; mf++) {
                    mma16816(accf[mf][nf], ah[mf], bh);
                    mma16816(accf[mf][nf], ah[mf], bl);
                    mma16816(accf[mf][nf], al[mf], bh);
                }
            }
        }
        __syncthreads();
    }

    // epilogue
    #pragma unroll
    for (int mf = 0; mf < 4; mf++) {
        int r0 = m0 + warp_m*64 + mf*16 + l4;
        int r1 = r0 + 8;
        #pragma unroll
        for (int nf = 0; nf < 4; nf++) {
            int c = n0 + warp_n*32 + nf*8 + lm*2;
            if (c >= N) continue;
            if (r0 < M) {
                float* p = C + (size_t)r0*N + c;
                float v0 = accf[mf][nf][0], v1 = accf[mf][nf][1];
                if (acc) { v0 += p[0]; v1 += p[1]; }
                p[0] = v0; p[1] = v1;
            }
            if (r1 < M) {
                float* p = C + (size_t)r1*N + c;
                float v2 = accf[mf][nf][2], v3 = accf[mf][nf][3];
                if (acc) { v2 += p[0]; v3 += p[1]; }
                p[0] = v2; p[1] = v3;
            }
        }
    }
}

// ================= small kernels =================
__global__ void rope_table_k() {
    int i = blockIdx.x*blockDim.x + threadIdx.x;
    if (i >= SEQ*32) return;
    int s = i >> 5, d = i & 31;
    double freq = exp(-((double)(2*d)/(double)HDIM) * log(10000.0));
    double a = (double)s * freq;
    g_cos[i] = (float)cos(a);
    g_sin[i] = (float)sin(a);
}

__global__ void embed_k(const int* __restrict__ ids, const int* __restrict__ iter,
                        const float* __restrict__ emb, const float* __restrict__ iter_emb,
                        float* __restrict__ x) {
    int i = blockIdx.x*blockDim.x + threadIdx.x;
    if (i >= NTOK*DIM) return;
    int tok = i / DIM, d = i - tok*DIM;
    int it = iter[0];
    float v = emb[(size_t)ids[tok]*DIM + d];
    if (it < 8) v += iter_emb[(size_t)it*DIM + d];
    x[i] = v;
}

__global__ void split_k(const float* __restrict__ src, __half* __restrict__ hi,
                        __half* __restrict__ lo, int n) {
    int i = blockIdx.x*blockDim.x + threadIdx.x;
    if (i >= n) return;
    __half h, l; split_h(src[i], h, l);
    hi[i] = h; lo[i] = l;
}

__global__ void split_gu_k(const float* __restrict__ gw, const float* __restrict__ uw,
                           __half* __restrict__ hi, __half* __restrict__ lo) {
    int i = blockIdx.x*blockDim.x + threadIdx.x;
    if (i >= NLAYER*2*FFD*DIM) return;
    int l = i / (2*FFD*DIM), rr = i % (2*FFD*DIM);
    float a = (rr < FFD*DIM) ? gw[(size_t)l*FFD*DIM + rr] : uw[(size_t)l*FFD*DIM + (rr - FFD*DIM)];
    __half h, lw; split_h(a, h, lw);
    hi[i] = h; lo[i] = lw;
}

// rmsnorm -> fp16 hi/lo (optionally gathered rows)
__global__ void rmsnorm_split_k(const float* __restrict__ in, const float* __restrict__ w,
                                __half* __restrict__ ohi, __half* __restrict__ olo, int gather) {
    int r = blockIdx.x, t = threadIdx.x;   // 320 threads
    size_t src;
    if (gather) {
        int b = r / KSEL;
        src = ((size_t)b*SEQ + g_tk_idx[r]) * DIM;
    } else {
        src = (size_t)r * DIM;
    }
    float v = in[src + t];
    float sq = v*v;
    #pragma unroll
    for (int o = 16; o > 0; o >>= 1) sq += __shfl_down_sync(0xffffffffu, sq, o);
    __shared__ float wsum[10];
    __shared__ float s_inv;
    if ((t & 31) == 0) wsum[t >> 5] = sq;
    __syncthreads();
    if (t == 0) {
        float s = 0.f;
        #pragma unroll
        for (int i = 0; i < 10; i++) s += wsum[i];
        s_inv = rsqrtf(s / (float)DIM + 1e-6f);
    }
    __syncthreads();
    float y = w[t] * v * s_inv;
    __half h, l; split_h(y, h, l);
    ohi[(size_t)r*DIM + t] = h;
    olo[(size_t)r*DIM + t] = l;
}

// final rmsnorm -> fp32
__global__ void rmsnorm_plain_k(const float* __restrict__ in, const float* __restrict__ w,
                                float* __restrict__ out) {
    int r = blockIdx.x, t = threadIdx.x;
    float v = in[(size_t)r*DIM + t];
    float sq = v*v;
    #pragma unroll
    for (int o = 16; o > 0; o >>= 1) sq += __shfl_down_sync(0xffffffffu, sq, o);
    __shared__ float wsum[10];
    __shared__ float s_inv;
    if ((t & 31) == 0) wsum[t >> 5] = sq;
    __syncthreads();
    if (t == 0) {
        float s = 0.f;
        #pragma unroll
        for (int i = 0; i < 10; i++) s += wsum[i];
        s_inv = rsqrtf(s / (float)DIM + 1e-6f);
    }
    __syncthreads();
    out[(size_t)r*DIM + t] = w[t] * v * s_inv;
}

__global__ void rope_k(float* __restrict__ qkv) {
    int i = blockIdx.x*blockDim.x + threadIdx.x;
    if (i >= NTOK*320) return;
    int tok = i / 320, rest = i - tok*320;
    int part = rest / 160;
    int rr = rest - part*160;
    int h = rr >> 5, d = rr & 31;
    int s = tok & (SEQ-1);
    float c = g_cos[s*32 + d], sn = g_sin[s*32 + d];
    float* p = qkv + (size_t)tok*QKVN + part*DIM + h*HDIM;
    float a = p[d], b = p[d+32];
    p[d]    = a*c - b*sn;
    p[d+32] = b*c + a*sn;
}

// ---------------- flash attention (out split to fp16 hi/lo) ----------------
#define QT_OFF 0
#define VS_OFF (64*68)
#define KP_OFF (64*68 + 64*64)
#define ATTN_SMEM ((64*68 + 64*64 + 64*68)*4)
__global__ __launch_bounds__(256)
void fattn_k(const float* __restrict__ qkv, __half* __restrict__ ohi, __half* __restrict__ olo) {
    extern __shared__ float sm[];
    float* Qt = sm + QT_OFF;
    float* Vs = sm + VS_OFF;
    float* KP = sm + KP_OFF;
    int qt = gridDim.x - 1 - blockIdx.x;
    int h = blockIdx.y, b = blockIdx.z;
    int q0 = qt*64;
    int t = threadIdx.x;
    int ty = t >> 4, tx = t & 15;
    const float* base = qkv + (size_t)b*SEQ*QKVN;
    int lrow = t >> 2;
    int lf   = t & 3;

    {
        const float* src = base + (size_t)(q0 + lrow)*QKVN + h*HDIM;
        #pragma unroll
        for (int p = 0; p < 4; p++) {
            int c4 = lf + p*4;
            float4 v = *(const float4*)(src + c4*4);
            Qt[(c4*4+0)*68 + lrow] = v.x*0.125f;
            Qt[(c4*4+1)*68 + lrow] = v.y*0.125f;
            Qt[(c4*4+2)*68 + lrow] = v.z*0.125f;
            Qt[(c4*4+3)*68 + lrow] = v.w*0.125f;
        }
    }

    float o4[4][4], m[4], l[4];
    #pragma unroll
    for (int i = 0; i < 4; i++) {
        m[i] = -1e30f; l[i] = 0.f;
        #pragma unroll
        for (int j = 0; j < 4; j++) o4[i][j] = 0.f;
    }

    for (int kt = 0; kt <= qt; kt++) {
        int k0 = kt*64;
        __syncthreads();
        {
            const float* ksrc = base + (size_t)(k0 + lrow)*QKVN + DIM + h*HDIM;
            const float* vsrc = base + (size_t)(k0 + lrow)*QKVN + 2*DIM + h*HDIM;
            #pragma unroll
            for (int p = 0; p < 4; p++) {
                int c4 = lf + p*4;
                float4 kv = *(const float4*)(ksrc + c4*4);
                KP[(c4*4+0)*68 + lrow] = kv.x;
                KP[(c4*4+1)*68 + lrow] = kv.y;
                KP[(c4*4+2)*68 + lrow] = kv.z;
                KP[(c4*4+3)*68 + lrow] = kv.w;
                *(float4*)&Vs[lrow*64 + c4*4] = *(const float4*)(vsrc + c4*4);
            }
        }
        __syncthreads();
        float cacc[4][4];
        #pragma unroll
        for (int i = 0; i < 4; i++)
            #pragma unroll
            for (int j = 0; j < 4; j++) cacc[i][j] = 0.f;
        #pragma unroll 8
        for (int d = 0; d < 64; d++) {
            float4 a4 = *(const float4*)&Qt[d*68 + ty*4];
            float4 b4 = *(const float4*)&KP[d*68 + tx*4];
            float a[4] = {a4.x,a4.y,a4.z,a4.w};
            float bb[4] = {b4.x,b4.y,b4.z,b4.w};
            #pragma unroll
            for (int i = 0; i < 4; i++)
                #pragma unroll
                for (int j = 0; j < 4; j++)
                    cacc[i][j] += a[i]*bb[j];
        }
        if (kt == qt) {
            #pragma unroll
            for (int i = 0; i < 4; i++)
                #pragma unroll
                for (int j = 0; j < 4; j++)
                    if (tx*4+j > ty*4+i) cacc[i][j] = -1e30f;
        }
        float corr[4];
        #pragma unroll
        for (int i = 0; i < 4; i++) {
            float mx = fmaxf(fmaxf(cacc[i][0],cacc[i][1]), fmaxf(cacc[i][2],cacc[i][3]));
            #pragma unroll
            for (int o = 1; o < 16; o <<= 1) mx = fmaxf(mx, __shfl_xor_sync(0xffffffffu, mx, o));
            float mnew = fmaxf(m[i], mx);
            corr[i] = expf(m[i] - mnew);
            m[i] = mnew;
            float rs = 0.f;
            #pragma unroll
            for (int j = 0; j < 4; j++) {
                float pv = expf(cacc[i][j] - mnew);
                cacc[i][j] = pv;
                rs += pv;
            }
            #pragma unroll
            for (int o = 1; o < 16; o <<= 1) rs += __shfl_xor_sync(0xffffffffu, rs, o);
            l[i] = l[i]*corr[i] + rs;
            #pragma unroll
            for (int j = 0; j < 4; j++) o4[i][j] *= corr[i];
        }
        __syncthreads();
        #pragma unroll
        for (int i = 0; i < 4; i++)
            #pragma unroll
            for (int j = 0; j < 4; j++)
                KP[(tx*4+j)*68 + ty*4+i] = cacc[i][j];
        __syncthreads();
        #pragma unroll 8
        for (int j = 0; j < 64; j++) {
            float p0 = KP[j*68 + ty*4+0];
            float p1 = KP[j*68 + ty*4+1];
            float p2 = KP[j*68 + ty*4+2];
            float p3 = KP[j*68 + ty*4+3];
            float4 v4 = *(const float4*)&Vs[j*64 + tx*4];
            float vv[4] = {v4.x,v4.y,v4.z,v4.w};
            #pragma unroll
            for (int d2 = 0; d2 < 4; d2++) {
                o4[0][d2] += p0*vv[d2];
                o4[1][d2] += p1*vv[d2];
                o4[2][d2] += p2*vv[d2];
                o4[3][d2] += p3*vv[d2];
            }
        }
    }
    #pragma unroll
    for (int i = 0; i < 4; i++) {
        float inv = 1.f / l[i];
        __half h0, l0, h1, l1, h2, l2, h3, l3;
        split_h(o4[i][0]*inv, h0, l0);
        split_h(o4[i][1]*inv, h1, l1);
        split_h(o4[i][2]*inv, h2, l2);
        split_h(o4[i][3]*inv, h3, l3);
        size_t o = ((size_t)b*SEQ + q0 + ty*4+i)*DIM + h*HDIM + tx*4;
        *(__half2*)(ohi + o)     = __halves2half2(h0, h1);
        *(__half2*)(ohi + o + 2) = __halves2half2(h2, h3);
        *(__half2*)(olo + o)     = __halves2half2(l0, l1);
        *(__half2*)(olo + o + 2) = __halves2half2(l2, l3);
    }
}

// ---------------- router + topk ----------------
__global__ __launch_bounds__(256)
void router_prob_k(const float* __restrict__ x, const float* __restrict__ rw,
                   float* __restrict__ probs) {
    int tok = blockIdx.x*8 + (threadIdx.x >> 5);
    int lane = threadIdx.x & 31;
    if (tok >= NTOK) return;
    const float* row = x + (size_t)tok*DIM;
    float acc = 0.f;
    #pragma unroll
    for (int i = 0; i < 10; i++) acc += row[lane + 32*i]*rw[lane + 32*i];
    #pragma unroll
    for (int o = 16; o > 0; o >>= 1) acc += __shfl_xor_sync(0xffffffffu, acc, o);
    if (lane == 0) probs[tok] = 1.f/(1.f + expf(-acc));
}

__global__ __launch_bounds__(1024)
void topk_k(const float* __restrict__ probs) {
    int b = blockIdx.x, t = threadIdx.x;
    __shared__ float ps[SEQ];
    __shared__ int   is[SEQ];
    for (int s = t; s < SEQ; s += 1024) { ps[s] = probs[b*SEQ + s]; is[s] = s; }
    __syncthreads();
    for (int size = 2; size <= SEQ; size <<= 1) {
        for (int stride = size >> 1; stride > 0; stride >>= 1) {
            for (int i = t; i < SEQ; i += 1024) {
                int j = i ^ stride;
                if (j > i) {
                    bool up = ((i & size) == 0);
                    float pi = ps[i], pj = ps[j];
                    int ii = is[i], ij = is[j];
                    bool iBetter = (pi > pj) || (pi == pj && ii < ij);
                    if (iBetter != up) { ps[i] = pj; ps[j] = pi; is[i] = ij; is[j] = ii; }
                }
            }
            __syncthreads();
        }
    }
    for (int jj = t; jj < KSEL; jj += 1024) {
        g_tk_idx[b*KSEL + jj] = is[jj];
        g_tk_p[b*KSEL + jj]   = ps[jj];
    }
}

// silu(gate)*up from g_gu [NSEL,1728] -> fp16 hi/lo [NSEL,864]
__global__ void act_k(const float* __restrict__ gu, __half* __restrict__ hi,
                      __half* __restrict__ lo) {
    int i = blockIdx.x*blockDim.x + threadIdx.x;
    if (i >= NSEL*FFD) return;
    int r = i / FFD, j = i - r*FFD;
    float g = gu[(size_t)r*2*FFD + j];
    float u = gu[(size_t)r*2*FFD + FFD + j];
    float v = (g / (1.f + expf(-g))) * u;
    __half h, l; split_h(v, h, l);
    hi[i] = h; lo[i] = l;
}

__global__ void scatter_k(float* __restrict__ x, const float* __restrict__ mlp) {
    int i = blockIdx.x*blockDim.x + threadIdx.x;
    if (i >= NSEL*DIM) return;
    int g = i / DIM, d = i - g*DIM;
    int b = g / KSEL;
    int srow = g_tk_idx[g];
    x[((size_t)b*SEQ + srow)*DIM + d] += mlp[i] * g_tk_p[g];
}

// ================= host orchestration =================
#define GEMM_SMEM (65536 + 128)
static inline void launch_gemm(const __half* ahi, const __half* alo,
                               const __half* bhi, const __half* blo,
                               float* C, int M, int N, int K, int acc) {
    dim3 grid((N + 127)/128, (M + 127)/128);
    gemm_h3_k<<<grid, 256, GEMM_SMEM>>>(ahi, alo, bhi, blo, C, M, N, K, acc);
}

extern "C" void kernel_launch(void* const* d_in, const int* in_sizes, int n_in,
                              void* d_out, int out_size) {
    const int*   ids       = (const int*)d_in[0];
    const int*   iter      = (const int*)d_in[1];
    const float* emb       = (const float*)d_in[2];
    const float* iter_emb  = (const float*)d_in[3];
    const float* attn_norm = (const float*)d_in[4];
    const float* wqkv      = (const float*)d_in[5];
    const float* wo        = (const float*)d_in[6];
    const float* router    = (const float*)d_in[7];
    const float* mlp_norm  = (const float*)d_in[8];
    const float* gw        = (const float*)d_in[9];
    const float* uw        = (const float*)d_in[10];
    const float* dw        = (const float*)d_in[11];
    const float* fnorm     = (const float*)d_in[12];
    float* x = (float*)d_out;

    __half *shi, *slo, *whi, *wlo;
    float *pqkv, *pgu, *pmlp, *pprobs;
    cudaGetSymbolAddress((void**)&shi,  g_shi);
    cudaGetSymbolAddress((void**)&slo,  g_slo);
    cudaGetSymbolAddress((void**)&whi,  g_whi);
    cudaGetSymbolAddress((void**)&wlo,  g_wlo);
    cudaGetSymbolAddress((void**)&pqkv, g_qkv);
    cudaGetSymbolAddress((void**)&pgu,  g_gu);
    cudaGetSymbolAddress((void**)&pmlp, g_mlp);
    cudaGetSymbolAddress((void**)&pprobs, g_probs);

    cudaFuncSetAttribute(fattn_k, cudaFuncAttributeMaxDynamicSharedMemorySize, ATTN_SMEM);
    cudaFuncSetAttribute(gemm_h3_k, cudaFuncAttributeMaxDynamicSharedMemorySize, GEMM_SMEM);

    rope_table_k<<<(SEQ*32 + 255)/256, 256>>>();
    embed_k<<<(NTOK*DIM + 255)/256, 256>>>(ids, iter, emb, iter_emb, x);

    // weight splits (fp16 hi/lo)
    split_k<<<(LEN_QKV + 255)/256, 256>>>(wqkv, whi + OFF_QKV, wlo + OFF_QKV, LEN_QKV);
    split_k<<<(LEN_WO + 255)/256, 256>>>(wo, whi + OFF_WO, wlo + OFF_WO, LEN_WO);
    split_gu_k<<<(LEN_GU + 255)/256, 256>>>(gw, uw, whi + OFF_GU, wlo + OFF_GU);
    split_k<<<(LEN_DOWN + 255)/256, 256>>>(dw, whi + OFF_DOWN, wlo + OFF_DOWN, LEN_DOWN);

    for (int l = 0; l < NLAYER; l++) {
        const __half* qh = whi + OFF_QKV + (size_t)l*QKVN*DIM;
        const __half* ql = wlo + OFF_QKV + (size_t)l*QKVN*DIM;
        const __half* oh = whi + OFF_WO + (size_t)l*DIM*DIM;
        const __half* ol = wlo + OFF_WO + (size_t)l*DIM*DIM;
        const __half* gh = whi + OFF_GU + (size_t)l*2*FFD*DIM;
        const __half* gl = wlo + OFF_GU + (size_t)l*2*FFD*DIM;
        const __half* dh = whi + OFF_DOWN + (size_t)l*DIM*FFD;
        const __half* dl = wlo + OFF_DOWN + (size_t)l*DIM*FFD;

        rmsnorm_split_k<<<NTOK, DIM>>>(x, attn_norm + (size_t)l*DIM, shi, slo, 0);
        launch_gemm(shi, slo, qh, ql, pqkv, NTOK, QKVN, DIM, 0);
        rope_k<<<(NTOK*320 + 255)/256, 256>>>(pqkv);
        fattn_k<<<dim3(SEQ/64, NHEAD, BATCH), 256, ATTN_SMEM>>>(pqkv, shi, slo);
        launch_gemm(shi, slo, oh, ol, x, NTOK, DIM, DIM, 1);

        router_prob_k<<<(NTOK+7)/8, 256>>>(x, router + (size_t)l*DIM, pprobs);
        topk_k<<<BATCH, 1024>>>(pprobs);

        rmsnorm_split_k<<<NSEL, DIM>>>(x, mlp_norm + (size_t)l*DIM, shi, slo, 1);
        launch_gemm(shi, slo, gh, gl, pgu, NSEL, 2*FFD, DIM, 0);
        act_k<<<(NSEL*FFD + 255)/256, 256>>>(pgu, shi, slo);
        launch_gemm(shi, slo, dh, dl, pmlp, NSEL, DIM, FFD, 0);
        scatter_k<<<(NSEL*DIM + 255)/256, 256>>>(x, pmlp);
    }

    rmsnorm_plain_k<<<NTOK, DIM>>>(x, fnorm, x);
}

// round 6
// speedup vs baseline: 6.8857x; 1.3480x over previous
#include <cuda_runtime.h>
#include <cuda_fp16.h>
#include <math.h>
#include <stdint.h>

#define BATCH 8
#define SEQ   2048
#define DIM   320
#define NHEAD 5
#define HDIM  64
#define FFD   864
#define NLAYER 6
#define KSEL  1638
#define NTOK  (BATCH*SEQ)      // 16384
#define NSEL  (BATCH*KSEL)     // 13104
#define QKVN  (3*DIM)          // 960

// weight split buffer offsets (elements)
#define OFF_QKV  0
#define LEN_QKV  (NLAYER*QKVN*DIM)
#define OFF_WO   (OFF_QKV + LEN_QKV)
#define LEN_WO   (NLAYER*DIM*DIM)
#define OFF_GU   (OFF_WO + LEN_WO)
#define LEN_GU   (NLAYER*2*FFD*DIM)
#define OFF_DOWN (OFF_GU + LEN_GU)
#define LEN_DOWN (NLAYER*DIM*FFD)
#define W_TOTAL  (OFF_DOWN + LEN_DOWN)

// ---------------- scratch ----------------
__device__ __half g_shi[(size_t)NSEL*FFD];
__device__ __half g_slo[(size_t)NSEL*FFD];
__device__ __half g_whi[W_TOTAL];
__device__ __half g_wlo[W_TOTAL];
__device__ float g_qkv[(size_t)NTOK*QKVN];
__device__ float g_gu[(size_t)NSEL*2*FFD];
__device__ float g_mlp[(size_t)NSEL*DIM];
__device__ __half g_qkh[(size_t)NTOK*2*DIM];   // [tok][q(320)|k(320)] roped, q pre-scaled
__device__ __half g_qkl[(size_t)NTOK*2*DIM];
__device__ __half g_vth[(size_t)BATCH*NHEAD*HDIM*SEQ];  // V transposed [b][h][d][s]
__device__ __half g_vtl[(size_t)BATCH*NHEAD*HDIM*SEQ];
__device__ float g_cos[SEQ*32];
__device__ float g_sin[SEQ*32];
__device__ int   g_tk_idx[BATCH*KSEL];
__device__ float g_tk_p[BATCH*KSEL];
__device__ float g_probs[NTOK];

__device__ __forceinline__ void split_h(float v, __half& h, __half& l) {
    h = __float2half_rn(v);
    l = __float2half_rn(v - __half2float(h));
}

// ================= PTX helpers =================
__device__ __forceinline__ uint32_t smem_u32(const void* p) {
    uint32_t a;
    asm("{ .reg .u64 t; cvta.to.shared.u64 t, %1; cvt.u32.u64 %0, t; }" : "=r"(a) : "l"(p));
    return a;
}
__device__ __forceinline__ void cp16(uint32_t dst, const void* src) {
    asm volatile("cp.async.cg.shared.global [%0], [%1], 16;" :: "r"(dst), "l"(src) : "memory");
}
__device__ __forceinline__ uint32_t lds32(uint32_t addr) {
    uint32_t v;
    asm volatile("ld.shared.b32 %0, [%1];" : "=r"(v) : "r"(addr));
    return v;
}
__device__ __forceinline__ void mma16816(float* c, const uint32_t* a, const uint32_t* b) {
    asm volatile("mma.sync.aligned.m16n8k16.row.col.f32.f16.f16.f32 "
        "{%0,%1,%2,%3}, {%4,%5,%6,%7}, {%8,%9}, {%0,%1,%2,%3};"
        : "+f"(c[0]), "+f"(c[1]), "+f"(c[2]), "+f"(c[3])
        : "r"(a[0]), "r"(a[1]), "r"(a[2]), "r"(a[3]), "r"(b[0]), "r"(b[1]));
}

// ================= fp16x3 tensor-core GEMM (3-stage) =================
__global__ __launch_bounds__(256)
void gemm_h3_k(const __half* __restrict__ Ahi, const __half* __restrict__ Alo,
               const __half* __restrict__ Bhi, const __half* __restrict__ Blo,
               float* __restrict__ C, int M, int N, int K, int acc)
{
    extern __shared__ char smem_raw[];
    uint32_t sb = (smem_u32(smem_raw) + 127u) & ~127u;

    const int t = threadIdx.x, lane = t & 31, wid = t >> 5;
    const int warp_m = wid & 1, warp_n = wid >> 1;
    const int m0 = blockIdx.y*128, n0 = blockIdx.x*128;
    const int T = K >> 5;
    const int l4 = lane >> 2, lm = lane & 3;

    const int lrow = t >> 1;
    const int lhalf = t & 1;
    const int aRow = min(m0 + lrow, M-1);
    const int bRow = min(n0 + lrow, N-1);
    const __half* aSrc = (lhalf ? Alo : Ahi) + (size_t)aRow*K;
    const __half* bSrc = (lhalf ? Blo : Bhi) + (size_t)bRow*K;
    uint32_t aDstBase = sb + (uint32_t)lrow*128u;
    uint32_t bDstBase = sb + 16384u + (uint32_t)lrow*128u;

    auto load_stage = [&](int kt, int s) {
        uint32_t so = (uint32_t)s*32768u;
        int k0 = kt*32;
        #pragma unroll
        for (int c4 = 0; c4 < 4; c4++) {
            int chunk = lhalf*4 + c4;
            uint32_t phys = (uint32_t)((chunk ^ (lrow & 7)) * 16);
            cp16(aDstBase + so + phys, aSrc + k0 + c4*8);
            cp16(bDstBase + so + phys, bSrc + k0 + c4*8);
        }
        asm volatile("cp.async.commit_group;" ::: "memory");
    };

    float accf[4][4][4];
    #pragma unroll
    for (int i = 0; i < 4; i++)
        #pragma unroll
        for (int j = 0; j < 4; j++)
            #pragma unroll
            for (int r = 0; r < 4; r++) accf[i][j][r] = 0.f;

    load_stage(0, 0);
    if (T > 1) load_stage(1, 1);

    for (int kt = 0; kt < T; kt++) {
        int s = kt % 3;
        if (kt + 2 < T) {
            load_stage(kt + 2, (kt + 2) % 3);
            asm volatile("cp.async.wait_group 2;" ::: "memory");
        } else if (kt + 1 < T) {
            asm volatile("cp.async.wait_group 1;" ::: "memory");
        } else {
            asm volatile("cp.async.wait_group 0;" ::: "memory");
        }
        __syncthreads();
        uint32_t Ab = sb + (uint32_t)s*32768u;
        uint32_t Bb = Ab + 16384u;
        #pragma unroll
        for (int ks = 0; ks < 2; ks++) {
            uint32_t ah[4][4], al[4][4];
            #pragma unroll
            for (int mf = 0; mf < 4; mf++) {
                int r0 = warp_m*64 + mf*16 + l4;
                int r1 = r0 + 8;
                int ch = ks*2, cl = ks*2 + 1;
                uint32_t a0 = Ab + (uint32_t)(r0*128) + (uint32_t)(lm*4);
                uint32_t a1 = Ab + (uint32_t)(r1*128) + (uint32_t)(lm*4);
                ah[mf][0] = lds32(a0 + (uint32_t)(((ch  ) ^ (r0&7))*16));
                ah[mf][1] = lds32(a1 + (uint32_t)(((ch  ) ^ (r1&7))*16));
                ah[mf][2] = lds32(a0 + (uint32_t)(((cl  ) ^ (r0&7))*16));
                ah[mf][3] = lds32(a1 + (uint32_t)(((cl  ) ^ (r1&7))*16));
                al[mf][0] = lds32(a0 + (uint32_t)(((ch+4) ^ (r0&7))*16));
                al[mf][1] = lds32(a1 + (uint32_t)(((ch+4) ^ (r1&7))*16));
                al[mf][2] = lds32(a0 + (uint32_t)(((cl+4) ^ (r0&7))*16));
                al[mf][3] = lds32(a1 + (uint32_t)(((cl+4) ^ (r1&7))*16));
            }
            #pragma unroll
            for (int nf = 0; nf < 4; nf++) {
                int cB = warp_n*32 + nf*8 + l4;
                int ch = ks*2, cl = ks*2 + 1;
                uint32_t bbase = Bb + (uint32_t)(cB*128) + (uint32_t)(lm*4);
                uint32_t bh[2], bl[2];
                bh[0] = lds32(bbase + (uint32_t)(((ch  ) ^ (cB&7))*16));
                bh[1] = lds32(bbase + (uint32_t)(((cl  ) ^ (cB&7))*16));
                bl[0] = lds32(bbase + (uint32_t)(((ch+4) ^ (cB&7))*16));
                bl[1] = lds32(bbase + (uint32_t)(((cl+4) ^ (cB&7))*16));
                #pragma unroll
                for (int mf = 0; mf < 4; mf++) {
                    mma16816(accf[mf][nf], ah[mf], bh);
                    mma16816(accf[mf][nf], ah[mf], bl);
                    mma16816(accf[mf][nf], al[mf], bh);
                }
            }
        }
        __syncthreads();
    }

    #pragma unroll
    for (int mf = 0; mf < 4; mf++) {
        int r0 = m0 + warp_m*64 + mf*16 + l4;
        int r1 = r0 + 8;
        #pragma unroll
        for (int nf = 0; nf < 4; nf++) {
            int c = n0 + warp_n*32 + nf*8 + lm*2;
            if (c >= N) continue;
            if (r0 < M) {
                float* p = C + (size_t)r0*N + c;
                float v0 = accf[mf][nf][0], v1 = accf[mf][nf][1];
                if (acc) { v0 += p[0]; v1 += p[1]; }
                p[0] = v0; p[1] = v1;
            }
            if (r1 < M) {
                float* p = C + (size_t)r1*N + c;
                float v2 = accf[mf][nf][2], v3 = accf[mf][nf][3];
                if (acc) { v2 += p[0]; v3 += p[1]; }
                p[0] = v2; p[1] = v3;
            }
        }
    }
}

// ================= small kernels =================
__global__ void rope_table_k() {
    int i = blockIdx.x*blockDim.x + threadIdx.x;
    if (i >= SEQ*32) return;
    int s = i >> 5, d = i & 31;
    double freq = exp(-((double)(2*d)/(double)HDIM) * log(10000.0));
    double a = (double)s * freq;
    g_cos[i] = (float)cos(a);
    g_sin[i] = (float)sin(a);
}

__global__ void embed_k(const int* __restrict__ ids, const int* __restrict__ iter,
                        const float* __restrict__ emb, const float* __restrict__ iter_emb,
                        float* __restrict__ x) {
    int i = blockIdx.x*blockDim.x + threadIdx.x;
    if (i >= NTOK*DIM) return;
    int tok = i / DIM, d = i - tok*DIM;
    int it = iter[0];
    float v = emb[(size_t)ids[tok]*DIM + d];
    if (it < 8) v += iter_emb[(size_t)it*DIM + d];
    x[i] = v;
}

__global__ void split_k(const float* __restrict__ src, __half* __restrict__ hi,
                        __half* __restrict__ lo, int n) {
    int i = blockIdx.x*blockDim.x + threadIdx.x;
    if (i >= n) return;
    __half h, l; split_h(src[i], h, l);
    hi[i] = h; lo[i] = l;
}

__global__ void split_gu_k(const float* __restrict__ gw, const float* __restrict__ uw,
                           __half* __restrict__ hi, __half* __restrict__ lo) {
    int i = blockIdx.x*blockDim.x + threadIdx.x;
    if (i >= NLAYER*2*FFD*DIM) return;
    int l = i / (2*FFD*DIM), rr = i % (2*FFD*DIM);
    float a = (rr < FFD*DIM) ? gw[(size_t)l*FFD*DIM + rr] : uw[(size_t)l*FFD*DIM + (rr - FFD*DIM)];
    __half h, lw; split_h(a, h, lw);
    hi[i] = h; lo[i] = lw;
}

__global__ void rmsnorm_split_k(const float* __restrict__ in, const float* __restrict__ w,
                                __half* __restrict__ ohi, __half* __restrict__ olo, int gather) {
    int r = blockIdx.x, t = threadIdx.x;   // 320 threads
    size_t src;
    if (gather) {
        int b = r / KSEL;
        src = ((size_t)b*SEQ + g_tk_idx[r]) * DIM;
    } else {
        src = (size_t)r * DIM;
    }
    float v = in[src + t];
    float sq = v*v;
    #pragma unroll
    for (int o = 16; o > 0; o >>= 1) sq += __shfl_down_sync(0xffffffffu, sq, o);
    __shared__ float wsum[10];
    __shared__ float s_inv;
    if ((t & 31) == 0) wsum[t >> 5] = sq;
    __syncthreads();
    if (t == 0) {
        float s = 0.f;
        #pragma unroll
        for (int i = 0; i < 10; i++) s += wsum[i];
        s_inv = rsqrtf(s / (float)DIM + 1e-6f);
    }
    __syncthreads();
    float y = w[t] * v * s_inv;
    __half h, l; split_h(y, h, l);
    ohi[(size_t)r*DIM + t] = h;
    olo[(size_t)r*DIM + t] = l;
}

__global__ void rmsnorm_plain_k(const float* __restrict__ in, const float* __restrict__ w,
                                float* __restrict__ out) {
    int r = blockIdx.x, t = threadIdx.x;
    float v = in[(size_t)r*DIM + t];
    float sq = v*v;
    #pragma unroll
    for (int o = 16; o > 0; o >>= 1) sq += __shfl_down_sync(0xffffffffu, sq, o);
    __shared__ float wsum[10];
    __shared__ float s_inv;
    if ((t & 31) == 0) wsum[t >> 5] = sq;
    __syncthreads();
    if (t == 0) {
        float s = 0.f;
        #pragma unroll
        for (int i = 0; i < 10; i++) s += wsum[i];
        s_inv = rsqrtf(s / (float)DIM + 1e-6f);
    }
    __syncthreads();
    out[(size_t)r*DIM + t] = w[t] * v * s_inv;
}

// ---- rope + split q/k + transpose/split v ----
// grid (SEQ/64, NHEAD, BATCH), 256 threads
__global__ __launch_bounds__(256)
void rope_split_k(const float* __restrict__ qkv) {
    __shared__ float vt[64][65];
    int st = blockIdx.x*64, h = blockIdx.y, b = blockIdx.z;
    int t = threadIdx.x;
    const float* base = qkv + ((size_t)b*SEQ + st)*QKVN;

    // V tile [s][d] -> smem [d][s]
    #pragma unroll
    for (int k = 0; k < 16; k++) {
        int i = t + k*256;
        int s = i >> 6, d = i & 63;
        vt[d][s] = base[(size_t)s*QKVN + 2*DIM + h*HDIM + d];
    }
    __syncthreads();
    // write vth/vtl [b][h][d][st+s]
    {
        size_t vbase = ((size_t)(b*NHEAD + h))*HDIM*SEQ;
        #pragma unroll
        for (int k = 0; k < 16; k++) {
            int i = t + k*256;
            int d = i >> 6, s = i & 63;
            float v = vt[d][s];
            __half hh, ll; split_h(v, hh, ll);
            size_t o = vbase + (size_t)d*SEQ + st + s;
            g_vth[o] = hh; g_vtl[o] = ll;
        }
    }
    // rope q, k
    #pragma unroll
    for (int part = 0; part < 2; part++) {
        #pragma unroll
        for (int k = 0; k < 8; k++) {
            int i = t + k*256;         // 2048 items: tok(64) x pair(32)
            int tok = i >> 5, d = i & 31;
            int s = st + tok;
            float c = g_cos[s*32 + d], sn = g_sin[s*32 + d];
            const float* p = base + (size_t)tok*QKVN + part*DIM + h*HDIM;
            float a = p[d], bb = p[d+32];
            float o0 = a*c - bb*sn;
            float o1 = bb*c + a*sn;
            if (part == 0) { o0 *= 0.125f; o1 *= 0.125f; }
            size_t ob = ((size_t)b*SEQ + s)*(2*DIM) + part*DIM + h*HDIM;
            __half h0, l0, h1, l1;
            split_h(o0, h0, l0); split_h(o1, h1, l1);
            g_qkh[ob + d] = h0;      g_qkl[ob + d] = l0;
            g_qkh[ob + d + 32] = h1; g_qkl[ob + d + 32] = l1;
        }
    }
}

// ---------------- tensor-core flash attention ----------------
// block per (b, h, 64-q-tile), 4 warps (128 thr). fp16 hi/lo x3 everywhere.
// smem (bytes): Qh 8K, Ql 8K, then 2 stages of {Kh,Kl,Vth,Vtl} 8K each.
#define FA_SMEM (16384 + 2*32768)
__global__ __launch_bounds__(128)
void fattn_tc_k(__half* __restrict__ ohi, __half* __restrict__ olo) {
    extern __shared__ char smem_raw[];
    uint32_t sb = smem_u32(smem_raw);
    const uint32_t QH = sb, QL = sb + 8192;
    const int t = threadIdx.x, lane = t & 31, warp = t >> 5;
    const int l4 = lane >> 2, lm = lane & 3;
    const int wr = warp*16;
    const int qt = gridDim.x - 1 - blockIdx.x;
    const int h = blockIdx.y, b = blockIdx.z;
    const int q0 = qt*64;

    const int lr = t & 63;          // row loaded by this thread
    const int cg = t >> 6;          // chunk group 0..1 (chunks cg*4..cg*4+3)

    auto cp_row = [&](uint32_t dstBase, const __half* src) {
        #pragma unroll
        for (int c4 = 0; c4 < 4; c4++) {
            int c = cg*4 + c4;
            cp16(dstBase + (uint32_t)(lr*128) + (uint32_t)(((c ^ (lr&7)))*16), src + c*8);
        }
    };

    // load Q (hi+lo)
    {
        size_t qoff = ((size_t)b*SEQ + q0 + lr)*(2*DIM) + h*HDIM;
        cp_row(QH, g_qkh + qoff);
        cp_row(QL, g_qkl + qoff);
    }
    size_t vtb = ((size_t)(b*NHEAD + h))*HDIM*SEQ + (size_t)lr*SEQ;

    auto load_stage = [&](int kt, int s) {
        uint32_t sbase = sb + 16384u + (uint32_t)s*32768u;
        int k0 = kt*64;
        size_t koff = ((size_t)b*SEQ + k0 + lr)*(2*DIM) + DIM + h*HDIM;
        cp_row(sbase,          g_qkh + koff);
        cp_row(sbase + 8192u,  g_qkl + koff);
        cp_row(sbase + 16384u, g_vth + vtb + k0);
        cp_row(sbase + 24576u, g_vtl + vtb + k0);
        asm volatile("cp.async.commit_group;" ::: "memory");
    };

    load_stage(0, 0);

    float oacc[8][4];
    #pragma unroll
    for (int i = 0; i < 8; i++)
        #pragma unroll
        for (int j = 0; j < 4; j++) oacc[i][j] = 0.f;
    float m0 = -1e30f, m1 = -1e30f, l0 = 0.f, l1 = 0.f;

    for (int kt = 0; kt <= qt; kt++) {
        int s = kt & 1;
        if (kt < qt) {
            load_stage(kt + 1, s ^ 1);
            asm volatile("cp.async.wait_group 1;" ::: "memory");
        } else {
            asm volatile("cp.async.wait_group 0;" ::: "memory");
        }
        __syncthreads();
        uint32_t KHs = sb + 16384u + (uint32_t)s*32768u;
        uint32_t KLs = KHs + 8192u, VHs = KHs + 16384u, VLs = KHs + 24576u;

        // ---- S = Q K^T (fp16x3) ----
        float sacc[8][4];
        #pragma unroll
        for (int i = 0; i < 8; i++)
            #pragma unroll
            for (int j = 0; j < 4; j++) sacc[i][j] = 0.f;

        #pragma unroll
        for (int ks = 0; ks < 4; ks++) {
            int kb = ks*32 + lm*4;
            uint32_t aqh[4], aql[4];
            int r0 = wr + l4, r1 = r0 + 8;
            int c0 = kb >> 4, o0 = kb & 15;
            aqh[0] = lds32(QH + (uint32_t)(r0*128) + (uint32_t)(((c0   ^ (r0&7)))*16) + o0);
            aqh[1] = lds32(QH + (uint32_t)(r1*128) + (uint32_t)(((c0   ^ (r1&7)))*16) + o0);
            aqh[2] = lds32(QH + (uint32_t)(r0*128) + (uint32_t)((((c0+1) ^ (r0&7)))*16) + o0);
            aqh[3] = lds32(QH + (uint32_t)(r1*128) + (uint32_t)((((c0+1) ^ (r1&7)))*16) + o0);
            aql[0] = lds32(QL + (uint32_t)(r0*128) + (uint32_t)(((c0   ^ (r0&7)))*16) + o0);
            aql[1] = lds32(QL + (uint32_t)(r1*128) + (uint32_t)(((c0   ^ (r1&7)))*16) + o0);
            aql[2] = lds32(QL + (uint32_t)(r0*128) + (uint32_t)((((c0+1) ^ (r0&7)))*16) + o0);
            aql[3] = lds32(QL + (uint32_t)(r1*128) + (uint32_t)((((c0+1) ^ (r1&7)))*16) + o0);
            #pragma unroll
            for (int nf = 0; nf < 8; nf++) {
                int rb = nf*8 + l4;
                uint32_t bh[2], bl[2];
                bh[0] = lds32(KHs + (uint32_t)(rb*128) + (uint32_t)(((c0   ^ (rb&7)))*16) + o0);
                bh[1] = lds32(KHs + (uint32_t)(rb*128) + (uint32_t)((((c0+1) ^ (rb&7)))*16) + o0);
                bl[0] = lds32(KLs + (uint32_t)(rb*128) + (uint32_t)(((c0   ^ (rb&7)))*16) + o0);
                bl[1] = lds32(KLs + (uint32_t)(rb*128) + (uint32_t)((((c0+1) ^ (rb&7)))*16) + o0);
                mma16816(sacc[nf], aqh, bh);
                mma16816(sacc[nf], aqh, bl);
                mma16816(sacc[nf], aql, bh);
            }
        }

        // causal mask on diagonal tile
        if (kt == qt) {
            int r0 = wr + l4, r1 = r0 + 8;
            #pragma unroll
            for (int nf = 0; nf < 8; nf++) {
                int c = nf*8 + lm*2;
                if (c     > r0) sacc[nf][0] = -1e30f;
                if (c + 1 > r0) sacc[nf][1] = -1e30f;
                if (c     > r1) sacc[nf][2] = -1e30f;
                if (c + 1 > r1) sacc[nf][3] = -1e30f;
            }
        }

        // ---- online softmax ----
        float mx0 = -1e30f, mx1 = -1e30f;
        #pragma unroll
        for (int nf = 0; nf < 8; nf++) {
            mx0 = fmaxf(mx0, fmaxf(sacc[nf][0], sacc[nf][1]));
            mx1 = fmaxf(mx1, fmaxf(sacc[nf][2], sacc[nf][3]));
        }
        mx0 = fmaxf(mx0, __shfl_xor_sync(0xffffffffu, mx0, 1));
        mx0 = fmaxf(mx0, __shfl_xor_sync(0xffffffffu, mx0, 2));
        mx1 = fmaxf(mx1, __shfl_xor_sync(0xffffffffu, mx1, 1));
        mx1 = fmaxf(mx1, __shfl_xor_sync(0xffffffffu, mx1, 2));
        float mn0 = fmaxf(m0, mx0), mn1 = fmaxf(m1, mx1);
        float cr0 = __expf(m0 - mn0), cr1 = __expf(m1 - mn1);
        m0 = mn0; m1 = mn1;
        float rs0 = 0.f, rs1 = 0.f;
        #pragma unroll
        for (int nf = 0; nf < 8; nf++) {
            sacc[nf][0] = __expf(sacc[nf][0] - mn0); rs0 += sacc[nf][0];
            sacc[nf][1] = __expf(sacc[nf][1] - mn0); rs0 += sacc[nf][1];
            sacc[nf][2] = __expf(sacc[nf][2] - mn1); rs1 += sacc[nf][2];
            sacc[nf][3] = __expf(sacc[nf][3] - mn1); rs1 += sacc[nf][3];
        }
        rs0 += __shfl_xor_sync(0xffffffffu, rs0, 1);
        rs0 += __shfl_xor_sync(0xffffffffu, rs0, 2);
        rs1 += __shfl_xor_sync(0xffffffffu, rs1, 1);
        rs1 += __shfl_xor_sync(0xffffffffu, rs1, 2);
        l0 = l0*cr0 + rs0;
        l1 = l1*cr1 + rs1;
        #pragma unroll
        for (int df = 0; df < 8; df++) {
            oacc[df][0] *= cr0; oacc[df][1] *= cr0;
            oacc[df][2] *= cr1; oacc[df][3] *= cr1;
        }

        // ---- O += P V (fp16x3) ----
        #pragma unroll
        for (int ks = 0; ks < 4; ks++) {
            uint32_t aPh[4], aPl[4];
            #pragma unroll
            for (int half2idx = 0; half2idx < 2; half2idx++) {
                int nf = 2*ks + half2idx;
                __half h0, e0, h1, e1, h2, e2, h3, e3;
                split_h(sacc[nf][0], h0, e0); split_h(sacc[nf][1], h1, e1);
                split_h(sacc[nf][2], h2, e2); split_h(sacc[nf][3], h3, e3);
                __half2 ph01 = __halves2half2(h0, h1), pl01 = __halves2half2(e0, e1);
                __half2 ph23 = __halves2half2(h2, h3), pl23 = __halves2half2(e2, e3);
                aPh[half2idx*2 + 0] = *(uint32_t*)&ph01;   // rows l4
                aPh[half2idx*2 + 1] = *(uint32_t*)&ph23;   // rows l4+8
                aPl[half2idx*2 + 0] = *(uint32_t*)&pl01;
                aPl[half2idx*2 + 1] = *(uint32_t*)&pl23;
            }
            // reorder into a0..a3: a0=rows l4 k0-7 (nf 2ks), a1=rows l4+8 k0-7,
            // a2=rows l4 k8-15 (nf 2ks+1), a3=rows l4+8 k8-15  -> already in place:
            // aPh = { (nf0 c01), (nf0 c23), (nf1 c01), (nf1 c23) } == {a0,a1,a2,a3}
            int kb = ks*32 + lm*4;
            int c0 = kb >> 4, o0 = kb & 15;
            #pragma unroll
            for (int df = 0; df < 8; df++) {
                int rb = df*8 + l4;
                uint32_t bh[2], bl[2];
                bh[0] = lds32(VHs + (uint32_t)(rb*128) + (uint32_t)(((c0   ^ (rb&7)))*16) + o0);
                bh[1] = lds32(VHs + (uint32_t)(rb*128) + (uint32_t)((((c0+1) ^ (rb&7)))*16) + o0);
                bl[0] = lds32(VLs + (uint32_t)(rb*128) + (uint32_t)(((c0   ^ (rb&7)))*16) + o0);
                bl[1] = lds32(VLs + (uint32_t)(rb*128) + (uint32_t)((((c0+1) ^ (rb&7)))*16) + o0);
                mma16816(oacc[df], aPh, bh);
                mma16816(oacc[df], aPh, bl);
                mma16816(oacc[df], aPl, bh);
            }
        }
        __syncthreads();
    }

    // epilogue: split to fp16 hi/lo for WO gemm
    float inv0 = 1.f / l0, inv1 = 1.f / l1;
    int r0 = q0 + wr + l4, r1 = r0 + 8;
    #pragma unroll
    for (int df = 0; df < 8; df++) {
        int d = df*8 + lm*2;
        float v0 = oacc[df][0]*inv0, v1 = oacc[df][1]*inv0;
        float v2 = oacc[df][2]*inv1, v3 = oacc[df][3]*inv1;
        __half h0, e0, h1, e1, h2, e2, h3, e3;
        split_h(v0, h0, e0); split_h(v1, h1, e1);
        split_h(v2, h2, e2); split_h(v3, h3, e3);
        size_t o0 = ((size_t)b*SEQ + r0)*DIM + h*HDIM + d;
        size_t o1 = ((size_t)b*SEQ + r1)*DIM + h*HDIM + d;
        *(__half2*)(ohi + o0) = __halves2half2(h0, h1);
        *(__half2*)(olo + o0) = __halves2half2(e0, e1);
        *(__half2*)(ohi + o1) = __halves2half2(h2, h3);
        *(__half2*)(olo + o1) = __halves2half2(e2, e3);
    }
}

// ---------------- router + topk ----------------
__global__ __launch_bounds__(256)
void router_prob_k(const float* __restrict__ x, const float* __restrict__ rw,
                   float* __restrict__ probs) {
    int tok = blockIdx.x*8 + (threadIdx.x >> 5);
    int lane = threadIdx.x & 31;
    if (tok >= NTOK) return;
    const float* row = x + (size_t)tok*DIM;
    float acc = 0.f;
    #pragma unroll
    for (int i = 0; i < 10; i++) acc += row[lane + 32*i]*rw[lane + 32*i];
    #pragma unroll
    for (int o = 16; o > 0; o >>= 1) acc += __shfl_xor_sync(0xffffffffu, acc, o);
    if (lane == 0) probs[tok] = 1.f/(1.f + expf(-acc));
}

__global__ __launch_bounds__(1024)
void topk_k(const float* __restrict__ probs) {
    int b = blockIdx.x, t = threadIdx.x;
    __shared__ float ps[SEQ];
    __shared__ int   is[SEQ];
    for (int s = t; s < SEQ; s += 1024) { ps[s] = probs[b*SEQ + s]; is[s] = s; }
    __syncthreads();
    for (int size = 2; size <= SEQ; size <<= 1) {
        for (int stride = size >> 1; stride > 0; stride >>= 1) {
            for (int i = t; i < SEQ; i += 1024) {
                int j = i ^ stride;
                if (j > i) {
                    bool up = ((i & size) == 0);
                    float pi = ps[i], pj = ps[j];
                    int ii = is[i], ij = is[j];
                    bool iBetter = (pi > pj) || (pi == pj && ii < ij);
                    if (iBetter != up) { ps[i] = pj; ps[j] = pi; is[i] = ij; is[j] = ii; }
                }
            }
            __syncthreads();
        }
    }
    for (int jj = t; jj < KSEL; jj += 1024) {
        g_tk_idx[b*KSEL + jj] = is[jj];
        g_tk_p[b*KSEL + jj]   = ps[jj];
    }
}

__global__ void act_k(const float* __restrict__ gu, __half* __restrict__ hi,
                      __half* __restrict__ lo) {
    int i = blockIdx.x*blockDim.x + threadIdx.x;
    if (i >= NSEL*FFD) return;
    int r = i / FFD, j = i - r*FFD;
    float g = gu[(size_t)r*2*FFD + j];
    float u = gu[(size_t)r*2*FFD + FFD + j];
    float v = (g / (1.f + expf(-g))) * u;
    __half h, l; split_h(v, h, l);
    hi[i] = h; lo[i] = l;
}

__global__ void scatter_k(float* __restrict__ x, const float* __restrict__ mlp) {
    int i = blockIdx.x*blockDim.x + threadIdx.x;
    if (i >= NSEL*DIM) return;
    int g = i / DIM, d = i - g*DIM;
    int b = g / KSEL;
    int srow = g_tk_idx[g];
    x[((size_t)b*SEQ + srow)*DIM + d] += mlp[i] * g_tk_p[g];
}

// ================= host orchestration =================
#define GEMM_SMEM (3*32768 + 128)
static inline void launch_gemm(const __half* ahi, const __half* alo,
                               const __half* bhi, const __half* blo,
                               float* C, int M, int N, int K, int acc) {
    dim3 grid((N + 127)/128, (M + 127)/128);
    gemm_h3_k<<<grid, 256, GEMM_SMEM>>>(ahi, alo, bhi, blo, C, M, N, K, acc);
}

extern "C" void kernel_launch(void* const* d_in, const int* in_sizes, int n_in,
                              void* d_out, int out_size) {
    const int*   ids       = (const int*)d_in[0];
    const int*   iter      = (const int*)d_in[1];
    const float* emb       = (const float*)d_in[2];
    const float* iter_emb  = (const float*)d_in[3];
    const float* attn_norm = (const float*)d_in[4];
    const float* wqkv      = (const float*)d_in[5];
    const float* wo        = (const float*)d_in[6];
    const float* router    = (const float*)d_in[7];
    const float* mlp_norm  = (const float*)d_in[8];
    const float* gw        = (const float*)d_in[9];
    const float* uw        = (const float*)d_in[10];
    const float* dw        = (const float*)d_in[11];
    const float* fnorm     = (const float*)d_in[12];
    float* x = (float*)d_out;

    __half *shi, *slo, *whi, *wlo;
    float *pqkv, *pgu, *pmlp, *pprobs;
    cudaGetSymbolAddress((void**)&shi,  g_shi);
    cudaGetSymbolAddress((void**)&slo,  g_slo);
    cudaGetSymbolAddress((void**)&whi,  g_whi);
    cudaGetSymbolAddress((void**)&wlo,  g_wlo);
    cudaGetSymbolAddress((void**)&pqkv, g_qkv);
    cudaGetSymbolAddress((void**)&pgu,  g_gu);
    cudaGetSymbolAddress((void**)&pmlp, g_mlp);
    cudaGetSymbolAddress((void**)&pprobs, g_probs);

    cudaFuncSetAttribute(fattn_tc_k, cudaFuncAttributeMaxDynamicSharedMemorySize, FA_SMEM);
    cudaFuncSetAttribute(gemm_h3_k, cudaFuncAttributeMaxDynamicSharedMemorySize, GEMM_SMEM);

    rope_table_k<<<(SEQ*32 + 255)/256, 256>>>();
    embed_k<<<(NTOK*DIM + 255)/256, 256>>>(ids, iter, emb, iter_emb, x);

    split_k<<<(LEN_QKV + 255)/256, 256>>>(wqkv, whi + OFF_QKV, wlo + OFF_QKV, LEN_QKV);
    split_k<<<(LEN_WO + 255)/256, 256>>>(wo, whi + OFF_WO, wlo + OFF_WO, LEN_WO);
    split_gu_k<<<(LEN_GU + 255)/256, 256>>>(gw, uw, whi + OFF_GU, wlo + OFF_GU);
    split_k<<<(LEN_DOWN + 255)/256, 256>>>(dw, whi + OFF_DOWN, wlo + OFF_DOWN, LEN_DOWN);

    for (int l = 0; l < NLAYER; l++) {
        const __half* qh = whi + OFF_QKV + (size_t)l*QKVN*DIM;
        const __half* ql = wlo + OFF_QKV + (size_t)l*QKVN*DIM;
        const __half* oh = whi + OFF_WO + (size_t)l*DIM*DIM;
        const __half* ol = wlo + OFF_WO + (size_t)l*DIM*DIM;
        const __half* gh = whi + OFF_GU + (size_t)l*2*FFD*DIM;
        const __half* gl = wlo + OFF_GU + (size_t)l*2*FFD*DIM;
        const __half* dh = whi + OFF_DOWN + (size_t)l*DIM*FFD;
        const __half* dl = wlo + OFF_DOWN + (size_t)l*DIM*FFD;

        rmsnorm_split_k<<<NTOK, DIM>>>(x, attn_norm + (size_t)l*DIM, shi, slo, 0);
        launch_gemm(shi, slo, qh, ql, pqkv, NTOK, QKVN, DIM, 0);
        rope_split_k<<<dim3(SEQ/64, NHEAD, BATCH), 256>>>(pqkv);
        fattn_tc_k<<<dim3(SEQ/64, NHEAD, BATCH), 128, FA_SMEM>>>(shi, slo);
        launch_gemm(shi, slo, oh, ol, x, NTOK, DIM, DIM, 1);

        router_prob_k<<<(NTOK+7)/8, 256>>>(x, router + (size_t)l*DIM, pprobs);
        topk_k<<<BATCH, 1024>>>(pprobs);

        rmsnorm_split_k<<<NSEL, DIM>>>(x, mlp_norm + (size_t)l*DIM, shi, slo, 1);
        launch_gemm(shi, slo, gh, gl, pgu, NSEL, 2*FFD, DIM, 0);
        act_k<<<(NSEL*FFD + 255)/256, 256>>>(pgu, shi, slo);
        launch_gemm(shi, slo, dh, dl, pmlp, NSEL, DIM, FFD, 0);
        scatter_k<<<(NSEL*DIM + 255)/256, 256>>>(x, pmlp);
    }

    rmsnorm_plain_k<<<NTOK, DIM>>>(x, fnorm, x);
}